// round 11
// baseline (speedup 1.0000x reference)
#include <cuda_runtime.h>

// RouterModel: N=32768 tokens, D=1024, P=2 paths.
// d = x . (W[:,0]-W[:,1]); path = d>=0 ? 0 : 1; gate = sigmoid(|d|)
// out = [x0 | x1 | xc], each [N, D] float32.
//
// Block-per-token, 128 threads, Blackwell 256-bit global accesses:
// thread t owns floats 8t..8t+7 of the row -> 1x ld.global.v8.f32 and
// 3x st.global.v8.f32 (LDG.E.256 / STG.E.256). Halves LDG/STG instruction
// count vs float4, cutting L1tex wavefront-queue pressure per byte.

#define N_TOK   32768
#define DHID    1024
#define THREADS 128   // DHID/8 v8-lanes per row

__global__ __launch_bounds__(THREADS) void router_kernel(
    const float* __restrict__ x, const float* __restrict__ W,
    float* __restrict__ out)
{
    const int n = blockIdx.x;
    const int t = threadIdx.x;

    // 256-bit load of this thread's 8-float slice of the token row.
    const float* xp = x + (size_t)n * DHID + 8 * t;
    float a0, a1, a2, a3, a4, a5, a6, a7;
    asm volatile("ld.global.v8.f32 {%0,%1,%2,%3,%4,%5,%6,%7}, [%8];"
                 : "=f"(a0), "=f"(a1), "=f"(a2), "=f"(a3),
                   "=f"(a4), "=f"(a5), "=f"(a6), "=f"(a7)
                 : "l"(xp));

    // W layout [D,2] row-major: (W0,W1) pairs interleaved. Rows 8t..8t+7
    // = float4 indices 4t..4t+3 (contiguous 64B, L1-hit after wave 1).
    const float4* w4 = reinterpret_cast<const float4*>(W);
    const float4 w0 = __ldg(w4 + 4 * t);
    const float4 w1 = __ldg(w4 + 4 * t + 1);
    const float4 w2 = __ldg(w4 + 4 * t + 2);
    const float4 w3 = __ldg(w4 + 4 * t + 3);

    // Partial dot with (W0 - W1), folded in registers.
    float p = a0 * (w0.x - w0.y) + a1 * (w0.z - w0.w)
            + a2 * (w1.x - w1.y) + a3 * (w1.z - w1.w)
            + a4 * (w2.x - w2.y) + a5 * (w2.z - w2.w)
            + a6 * (w3.x - w3.y) + a7 * (w3.z - w3.w);

    // Warp reduce, then 4-warp smem combine.
    #pragma unroll
    for (int o = 16; o > 0; o >>= 1)
        p += __shfl_xor_sync(0xffffffffu, p, o);

    __shared__ float s[THREADS / 32];
    const int wid = t >> 5, lid = t & 31;
    if (lid == 0) s[wid] = p;
    __syncthreads();

    float d = 0.0f;
    #pragma unroll
    for (int i = 0; i < THREADS / 32; i++) d += s[i];   // broadcast, conflict-free

    // gate = softmax max-prob = sigmoid(|d|); path 0 iff d >= 0 (argmax tie -> 0)
    const float g = 1.0f / (1.0f + __expf(-fabsf(d)));
    const float g0 = (d >= 0.0f) ? g : 0.0f;   // x0 gate
    const float g1 = (d >= 0.0f) ? 0.0f : g;   // x1 gate

    const size_t sect = (size_t)N_TOK * DHID;
    float* o0 = out + (size_t)n * DHID + 8 * t;          // x0 slice
    float* o1 = o0 + sect;                                // x1 slice
    float* oc = o0 + 2 * sect;                            // xc slice

    asm volatile("st.global.v8.f32 [%0], {%1,%2,%3,%4,%5,%6,%7,%8};"
                 :: "l"(o0),
                    "f"(a0*g0), "f"(a1*g0), "f"(a2*g0), "f"(a3*g0),
                    "f"(a4*g0), "f"(a5*g0), "f"(a6*g0), "f"(a7*g0)
                 : "memory");
    asm volatile("st.global.v8.f32 [%0], {%1,%2,%3,%4,%5,%6,%7,%8};"
                 :: "l"(o1),
                    "f"(a0*g1), "f"(a1*g1), "f"(a2*g1), "f"(a3*g1),
                    "f"(a4*g1), "f"(a5*g1), "f"(a6*g1), "f"(a7*g1)
                 : "memory");
    asm volatile("st.global.v8.f32 [%0], {%1,%2,%3,%4,%5,%6,%7,%8};"
                 :: "l"(oc),
                    "f"(a0*g), "f"(a1*g), "f"(a2*g), "f"(a3*g),
                    "f"(a4*g), "f"(a5*g), "f"(a6*g), "f"(a7*g)
                 : "memory");
}

extern "C" void kernel_launch(void* const* d_in, const int* in_sizes, int n_in,
                              void* d_out, int out_size) {
    const float* x = (const float*)d_in[0];   // [N, D] float32
    const float* W = (const float*)d_in[1];   // [D, 2] float32
    float* out = (float*)d_out;               // [3, N, D] float32

    router_kernel<<<N_TOK, THREADS>>>(x, W, out);
}